// round 1
// baseline (speedup 1.0000x reference)
#include <cuda_runtime.h>
#include <math.h>

// Problem constants
#define Bn 16
#define Nn 256
#define Fn 64
#define Hn 128

// Table constants
#define Tn 512
#define D_MAX 1.7320509f

// Scratch: per-feature univariate function table g_f(d), built per launch.
__device__ float g_table[Tn * Fn];

__device__ __forceinline__ float softplus_acc(float x) {
    // matches jax.nn.softplus = logaddexp(x, 0), stable for all x
    return fmaxf(x, 0.0f) + log1pf(expf(-fabsf(x)));
}

// ---------------------------------------------------------------------------
// Kernel 1: build g_table[k][f] = softplus( sum_h softplus(d_k*w1+b1)*W2[h,f] + b2[f] )
// grid = Tn blocks, block = Hn threads.
// ---------------------------------------------------------------------------
__global__ void build_table_kernel(const float* __restrict__ w1,
                                   const float* __restrict__ b1,
                                   const float* __restrict__ W2,
                                   const float* __restrict__ b2) {
    __shared__ float u[Hn];
    const int k = blockIdx.x;
    const int h = threadIdx.x;  // 0..127
    const float d = (float)k * (D_MAX / (float)(Tn - 1));
    u[h] = softplus_acc(fmaf(d, w1[h], b1[h]));
    __syncthreads();
    if (h < Fn) {
        float acc = b2[h];
#pragma unroll
        for (int hh = 0; hh < Hn; ++hh)
            acc = fmaf(u[hh], W2[hh * Fn + h], acc);
        g_table[k * Fn + h] = softplus_acc(acc);
    }
}

// ---------------------------------------------------------------------------
// Kernel 2: main reduction.
// grid = 128 CTAs (one per 32 output rows), block = 256 threads.
// Thread (fg = tid&15, ip = tid>>4) owns features [4fg,4fg+4) of rows
// {32*cta + 2*ip, 32*cta + 2*ip + 1}.
// ---------------------------------------------------------------------------
#define DROW 257  // padded row stride for distance tile (avoid bank conflicts)

__global__ void __launch_bounds__(256, 1)
mp_main_kernel(const float* __restrict__ r, const float* __restrict__ f,
               float* __restrict__ out) {
    extern __shared__ float sm[];
    float* tab = sm;                    // Tn*Fn   = 32768 floats (128 KB)
    float* fsm = tab + Tn * Fn;         // Nn*Fn   = 16384 floats (64 KB)
    float* dsm = fsm + Nn * Fn;         // 32*DROW =  8224 floats (~32 KB)

    const int tid = threadIdx.x;
    const int cta = blockIdx.x;             // 0..127
    const int b = cta >> 3;                 // 8 CTAs per batch element
    const int i0_local = (cta & 7) * 32;    // first local row of this tile

    // 1) stage r[b] (256x3 floats) into the f-tile area temporarily
    for (int e = tid; e < Nn * 3; e += 256)
        fsm[e] = r[b * Nn * 3 + e];
    __syncthreads();

    // 2) pre-scaled distances for the 32 tile rows vs all 256 j
    const float scale = (float)(Tn - 1) / D_MAX;
    for (int e = tid; e < 32 * Nn; e += 256) {
        const int il = e >> 8;
        const int j = e & 255;
        const int ig = i0_local + il;
        const float dx = fsm[ig * 3 + 0] - fsm[j * 3 + 0];
        const float dy = fsm[ig * 3 + 1] - fsm[j * 3 + 1];
        const float dz = fsm[ig * 3 + 2] - fsm[j * 3 + 2];
        const float s = fmaf(dx, dx, fmaf(dy, dy, dz * dz));
        float d;
        asm("sqrt.approx.f32 %0, %1;" : "=f"(d) : "f"(s));  // sqrt.approx(0)=0
        dsm[il * DROW + j] = d * scale;
    }
    __syncthreads();

    // 3) stage f[b] tile and the interpolation table (overwrites r staging)
    for (int e = tid; e < (Nn * Fn) / 4; e += 256)
        ((float4*)fsm)[e] = ((const float4*)(f + b * Nn * Fn))[e];
    for (int e = tid; e < (Tn * Fn) / 4; e += 256)
        ((float4*)tab)[e] = ((const float4*)g_table)[e];
    __syncthreads();

    // 4) main loop over j
    const int fg = (tid & 15) * 4;  // feature offset (0,4,...,60)
    const int ip = tid >> 4;        // 0..15 -> rows 2*ip, 2*ip+1
    const float* d0 = dsm + (ip * 2) * DROW;
    const float* d1 = d0 + DROW;
    const float* fjp = fsm + fg;
    const float* tabp = tab + fg;

    float4 acc0 = make_float4(0.f, 0.f, 0.f, 0.f);
    float4 acc1 = make_float4(0.f, 0.f, 0.f, 0.f);

#pragma unroll 4
    for (int j = 0; j < Nn; ++j) {
        const float u0 = d0[j];
        const float u1 = d1[j];
        const float4 fv = *(const float4*)(fjp + j * Fn);

        int k0 = (int)u0; k0 = min(k0, Tn - 2);
        int k1 = (int)u1; k1 = min(k1, Tn - 2);
        const float t0 = u0 - (float)k0;
        const float t1 = u1 - (float)k1;

        const float4 a0 = *(const float4*)(tabp + k0 * Fn);
        const float4 c0 = *(const float4*)(tabp + (k0 + 1) * Fn);
        const float4 a1 = *(const float4*)(tabp + k1 * Fn);
        const float4 c1 = *(const float4*)(tabp + (k1 + 1) * Fn);

        float g;
        g = fmaf(t0, c0.x - a0.x, a0.x); acc0.x = fmaf(g, fv.x, acc0.x);
        g = fmaf(t0, c0.y - a0.y, a0.y); acc0.y = fmaf(g, fv.y, acc0.y);
        g = fmaf(t0, c0.z - a0.z, a0.z); acc0.z = fmaf(g, fv.z, acc0.z);
        g = fmaf(t0, c0.w - a0.w, a0.w); acc0.w = fmaf(g, fv.w, acc0.w);

        g = fmaf(t1, c1.x - a1.x, a1.x); acc1.x = fmaf(g, fv.x, acc1.x);
        g = fmaf(t1, c1.y - a1.y, a1.y); acc1.y = fmaf(g, fv.y, acc1.y);
        g = fmaf(t1, c1.z - a1.z, a1.z); acc1.z = fmaf(g, fv.z, acc1.z);
        g = fmaf(t1, c1.w - a1.w, a1.w); acc1.w = fmaf(g, fv.w, acc1.w);
    }

    // 5) final softplus + store
    const int row0 = cta * 32 + ip * 2;  // global row index (b*N + i)
    float4 o0, o1;
    o0.x = softplus_acc(acc0.x); o0.y = softplus_acc(acc0.y);
    o0.z = softplus_acc(acc0.z); o0.w = softplus_acc(acc0.w);
    o1.x = softplus_acc(acc1.x); o1.y = softplus_acc(acc1.y);
    o1.z = softplus_acc(acc1.z); o1.w = softplus_acc(acc1.w);
    *(float4*)(out + row0 * Fn + fg) = o0;
    *(float4*)(out + (row0 + 1) * Fn + fg) = o1;
}

// ---------------------------------------------------------------------------
extern "C" void kernel_launch(void* const* d_in, const int* in_sizes, int n_in,
                              void* d_out, int out_size) {
    const float* r_batch = (const float*)d_in[0];  // [16,256,3]
    const float* f_batch = (const float*)d_in[1];  // [16,256,64]
    const float* w1 = (const float*)d_in[2];       // [128]
    const float* b1 = (const float*)d_in[3];       // [128]
    const float* W2 = (const float*)d_in[4];       // [128,64]
    const float* b2 = (const float*)d_in[5];       // [64]
    float* out = (float*)d_out;                    // [16,256,64]

    build_table_kernel<<<Tn, Hn>>>(w1, b1, W2, b2);

    const int smem_bytes = (Tn * Fn + Nn * Fn + 32 * DROW) * (int)sizeof(float);
    static bool attr_set = false;
    if (!attr_set) {
        cudaFuncSetAttribute(mp_main_kernel,
                             cudaFuncAttributeMaxDynamicSharedMemorySize,
                             smem_bytes);
        attr_set = true;
    }
    mp_main_kernel<<<(Bn * Nn) / 32, 256, smem_bytes>>>(r_batch, f_batch, out);
}